// round 4
// baseline (speedup 1.0000x reference)
#include <cuda_runtime.h>
#include <math.h>

#define B_   16
#define N_   2048
#define K_   16
#define EPS_ 1e-8f

// Output layout (tuple flattened in order):
//   psi_prime : B*N*2  floats  @ 0
//   features  : B*N*5  floats  @ 65536
//   knn_idx   : B*N*16 floats  @ 229376
#define PSI_OFF  0
#define FEAT_OFF (B_ * N_ * 2)
#define KNN_OFF  (B_ * N_ * 2 + B_ * N_ * 5)

// Packed per-point candidate data {x, y, sq, 0} for the KNN kernel.
__device__ float4 g_pk[B_ * N_];

// ---------------------------------------------------------------------------
// Kernel 1: features + encoder (tiny MLP) + packed-coord scratch.
// ---------------------------------------------------------------------------
__global__ void encode_kernel(const float* __restrict__ coords,
                              const float* __restrict__ demands,
                              const float* __restrict__ capacity,
                              const float* __restrict__ Wa,
                              const float* __restrict__ ba,
                              const float* __restrict__ W1,
                              const float* __restrict__ b1,
                              const float* __restrict__ W2,
                              const float* __restrict__ b2,
                              float* __restrict__ out)
{
    int b = blockIdx.y;
    int n = blockIdx.x * blockDim.x + threadIdx.x;
    if (n >= N_) return;

    __shared__ float sWa[10], sba[2], sW1[80], sb1[16], sW2[16], sb2_s;
    int t = threadIdx.x;
    if (t < 10) sWa[t] = Wa[t];
    if (t < 2)  sba[t] = ba[t];
    if (t < 80) sW1[t] = W1[t];
    if (t < 16) { sb1[t] = b1[t]; sW2[t] = W2[t]; }
    if (t == 0) sb2_s = b2[0];
    __syncthreads();

    const float* cp = coords + ((long long)b * N_ + n) * 2;
    float x = cp[0], y = cp[1];

    // packed scratch for knn; sq with the reference's rounding:
    // rn(rn(x*x) + rn(y*y))
    float sq = __fadd_rn(__fmul_rn(x, x), __fmul_rn(y, y));
    g_pk[b * N_ + n] = make_float4(x, y, sq, 0.0f);

    float dx0 = coords[(long long)b * N_ * 2 + 0];
    float dy0 = coords[(long long)b * N_ * 2 + 1];
    float rx = x - dx0, ry = y - dy0;
    float dist = sqrtf(rx * rx + ry * ry + EPS_);
    float ang  = atan2f(ry, rx);
    float dem  = demands[(long long)b * N_ + n] / capacity[b];

    float f0 = x, f1 = y, f2 = dem, f3 = dist, f4 = ang;

    float* fo = out + FEAT_OFF + ((long long)b * N_ + n) * 5;
    fo[0] = f0; fo[1] = f1; fo[2] = f2; fo[3] = f3; fo[4] = f4;

    float p0 = sba[0] + f0*sWa[0] + f1*sWa[1] + f2*sWa[2] + f3*sWa[3] + f4*sWa[4];
    float p1 = sba[1] + f0*sWa[5] + f1*sWa[6] + f2*sWa[7] + f3*sWa[8] + f4*sWa[9];
    float nrm = sqrtf(p0 * p0 + p1 * p1);
    float inv = 1.0f / (nrm + EPS_);
    p0 *= inv; p1 *= inv;

    float theta = sb2_s;
    #pragma unroll
    for (int h = 0; h < 16; ++h) {
        const float* w = sW1 + h * 5;
        float a = sb1[h] + f0*w[0] + f1*w[1] + f2*w[2] + f3*w[3] + f4*w[4];
        theta += tanhf(a) * sW2[h];
    }
    float c = cosf(theta), s = sinf(theta);

    float* po = out + PSI_OFF + ((long long)b * N_ + n) * 2;
    po[0] = c * p0 - s * p1;
    po[1] = s * p0 + c * p1;
}

// ---------------------------------------------------------------------------
// Kernel 2: KNN top-16. One thread per query, one warp per block (1024 blocks
// -> ~7 resident blocks/SM on 148 SMs, near-perfect balance, no smem).
// Candidates read as warp-uniform LDG.128 from L1-resident packed scratch.
// Loop unrolled x4 with batched loads (MLP=4) and a single min-gate.
//
// d2 arithmetic is bit-exact with the reference gemm lowering:
//   dot = fma(yq*yj, rn(xq*xj)); d2 = rn(rn(sqq+sqj) - rn(2*dot))
//
// INSERT is the R2-proven STABLE shift-insert: the whole suffix shifts down
// together, so equal-valued elements never leapfrog (matches jax.lax.top_k
// stable tie-break). The bubble-swap variant is NOT stable for the displaced
// element and fails at exact f32 ties.
// ---------------------------------------------------------------------------
#define D2_OF(c) \
    __fsub_rn(__fadd_rn(sqq, (c).z), \
              __fmul_rn(2.0f, __fmaf_rn(yq, (c).y, __fmul_rn(xq, (c).x))))

#define INSERT(dv, jv)                                       \
    do {                                                     \
        float d2v = (dv); int jj = (jv);                     \
        _Pragma("unroll")                                    \
        for (int k = K_ - 1; k > 0; --k) {                   \
            bool shift = d2v < bd[k - 1];                    \
            float sd = shift ? bd[k - 1] : d2v;              \
            int   si = shift ? bi[k - 1] : jj;               \
            bool place = d2v < bd[k];                        \
            bd[k] = place ? sd : bd[k];                      \
            bi[k] = place ? si : bi[k];                      \
        }                                                    \
        if (d2v < bd[0]) { bd[0] = d2v; bi[0] = jj; }        \
    } while (0)

__global__ void __launch_bounds__(32, 16)
knn_kernel(float* __restrict__ out_knn)
{
    int bid = blockIdx.x;          // 0..1023
    int b   = bid >> 6;            // batch
    int q   = ((bid & 63) << 5) + threadIdx.x;

    const float4* __restrict__ pk = g_pk + b * N_;
    float4 me = __ldg(&pk[q]);
    float xq = me.x, yq = me.y, sqq = me.z;

    float bd[K_];
    int   bi[K_];
    #pragma unroll
    for (int k = 0; k < K_; ++k) { bd[k] = 3.0e30f; bi[k] = 0; }

    for (int j = 0; j < N_; j += 4) {
        float4 c0 = __ldg(&pk[j]);
        float4 c1 = __ldg(&pk[j + 1]);
        float4 c2 = __ldg(&pk[j + 2]);
        float4 c3 = __ldg(&pk[j + 3]);

        float e0 = D2_OF(c0);
        float e1 = D2_OF(c1);
        float e2 = D2_OF(c2);
        float e3 = D2_OF(c3);

        // self-exclusion, hoisted to one rare branch per 4-group
        if ((unsigned)(q - j) < 4u) {
            if (q == j)     e0 = 2.0e30f;
            if (q == j + 1) e1 = 2.0e30f;
            if (q == j + 2) e2 = 2.0e30f;
            if (q == j + 3) e3 = 2.0e30f;
        }

        if (fminf(fminf(e0, e1), fminf(e2, e3)) < bd[K_ - 1]) {
            if (e0 < bd[K_ - 1]) INSERT(e0, j);
            if (e1 < bd[K_ - 1]) INSERT(e1, j + 1);
            if (e2 < bd[K_ - 1]) INSERT(e2, j + 2);
            if (e3 < bd[K_ - 1]) INSERT(e3, j + 3);
        }
    }

    float* o = out_knn + ((long long)b * N_ + q) * K_;
    #pragma unroll
    for (int k = 0; k < K_; ++k) o[k] = (float)bi[k];
}

// ---------------------------------------------------------------------------
extern "C" void kernel_launch(void* const* d_in, const int* in_sizes, int n_in,
                              void* d_out, int out_size)
{
    const float* coords   = (const float*)d_in[0];
    const float* demands  = (const float*)d_in[1];
    const float* capacity = (const float*)d_in[2];
    const float* Wa       = (const float*)d_in[3];
    const float* ba       = (const float*)d_in[4];
    const float* W1       = (const float*)d_in[5];
    const float* b1       = (const float*)d_in[6];
    const float* W2       = (const float*)d_in[7];
    const float* b2       = (const float*)d_in[8];
    float* out = (float*)d_out;

    encode_kernel<<<dim3(N_ / 256, B_), 256>>>(coords, demands, capacity,
                                               Wa, ba, W1, b1, W2, b2, out);
    knn_kernel<<<dim3(B_ * (N_ / 32)), 32>>>(out + KNN_OFF);
}

// round 5
// speedup vs baseline: 1.4499x; 1.4499x over previous
#include <cuda_runtime.h>
#include <math.h>

#define B_   16
#define N_   2048
#define K_   16
#define EPS_ 1e-8f

// Output layout (tuple flattened in order):
//   psi_prime : B*N*2  floats  @ 0
//   features  : B*N*5  floats  @ 65536
//   knn_idx   : B*N*16 floats  @ 229376
#define PSI_OFF  0
#define FEAT_OFF (B_ * N_ * 2)
#define KNN_OFF  (B_ * N_ * 2 + B_ * N_ * 5)

typedef unsigned long long u64;
typedef unsigned int u32;

#define SENT 0xFFFFFFFFFFFFFFFFull

// Packed per-point candidate data {x, y, sq, 0} for the KNN kernel.
__device__ float4 g_pk[B_ * N_];

// ---------------------------------------------------------------------------
// Kernel 1: features + encoder (tiny MLP) + packed-coord scratch.
// ---------------------------------------------------------------------------
__global__ void encode_kernel(const float* __restrict__ coords,
                              const float* __restrict__ demands,
                              const float* __restrict__ capacity,
                              const float* __restrict__ Wa,
                              const float* __restrict__ ba,
                              const float* __restrict__ W1,
                              const float* __restrict__ b1,
                              const float* __restrict__ W2,
                              const float* __restrict__ b2,
                              float* __restrict__ out)
{
    int b = blockIdx.y;
    int n = blockIdx.x * blockDim.x + threadIdx.x;
    if (n >= N_) return;

    __shared__ float sWa[10], sba[2], sW1[80], sb1[16], sW2[16], sb2_s;
    int t = threadIdx.x;
    if (t < 10) sWa[t] = Wa[t];
    if (t < 2)  sba[t] = ba[t];
    if (t < 80) sW1[t] = W1[t];
    if (t < 16) { sb1[t] = b1[t]; sW2[t] = W2[t]; }
    if (t == 0) sb2_s = b2[0];
    __syncthreads();

    const float* cp = coords + ((long long)b * N_ + n) * 2;
    float x = cp[0], y = cp[1];

    // packed scratch for knn; sq with the reference's rounding:
    // rn(rn(x*x) + rn(y*y))
    float sq = __fadd_rn(__fmul_rn(x, x), __fmul_rn(y, y));
    g_pk[b * N_ + n] = make_float4(x, y, sq, 0.0f);

    float dx0 = coords[(long long)b * N_ * 2 + 0];
    float dy0 = coords[(long long)b * N_ * 2 + 1];
    float rx = x - dx0, ry = y - dy0;
    float dist = sqrtf(rx * rx + ry * ry + EPS_);
    float ang  = atan2f(ry, rx);
    float dem  = demands[(long long)b * N_ + n] / capacity[b];

    float f0 = x, f1 = y, f2 = dem, f3 = dist, f4 = ang;

    float* fo = out + FEAT_OFF + ((long long)b * N_ + n) * 5;
    fo[0] = f0; fo[1] = f1; fo[2] = f2; fo[3] = f3; fo[4] = f4;

    float p0 = sba[0] + f0*sWa[0] + f1*sWa[1] + f2*sWa[2] + f3*sWa[3] + f4*sWa[4];
    float p1 = sba[1] + f0*sWa[5] + f1*sWa[6] + f2*sWa[7] + f3*sWa[8] + f4*sWa[9];
    float nrm = sqrtf(p0 * p0 + p1 * p1);
    float inv = 1.0f / (nrm + EPS_);
    p0 *= inv; p1 *= inv;

    float theta = sb2_s;
    #pragma unroll
    for (int h = 0; h < 16; ++h) {
        const float* w = sW1 + h * 5;
        float a = sb1[h] + f0*w[0] + f1*w[1] + f2*w[2] + f3*w[3] + f4*w[4];
        theta += tanhf(a) * sW2[h];
    }
    float c = cosf(theta), s = sinf(theta);

    float* po = out + PSI_OFF + ((long long)b * N_ + n) * 2;
    po[0] = c * p0 - s * p1;
    po[1] = s * p0 + c * p1;
}

// ---------------------------------------------------------------------------
// KNN helpers
// ---------------------------------------------------------------------------

// Monotone map: float bits -> u32 whose unsigned order == float order.
__device__ __forceinline__ u32 fmap(float f) {
    u32 b = __float_as_uint(f);
    return b ^ ((u32)((int)b >> 31) | 0x80000000u);
}

// key = (mapped d2) << 32 | j : ascending u64 order == (d2 asc, j asc).
__device__ __forceinline__ u64 pack_key(float d2, int j) {
    return ((u64)fmap(d2) << 32) | (u32)j;
}

// Warp-synchronized flush: sort the 16-slot buffer (sentinel-padded),
// merge into the sorted top-16 list L, tighten tau, reset buffer.
// All comparisons are on total-order u64 keys -> tie handling is exact.
__device__ __forceinline__ void flush16(u64* L, u64* lbuf, int& n, float& tau_f)
{
    u64 s[16];
    #pragma unroll
    for (int i = 0; i < 16; ++i) s[i] = lbuf[i];

    // Bitonic sort 16, ascending. Fully static after unroll.
    #pragma unroll
    for (int k = 2; k <= 16; k <<= 1) {
        #pragma unroll
        for (int j = k >> 1; j > 0; j >>= 1) {
            #pragma unroll
            for (int i = 0; i < 16; ++i) {
                int l = i ^ j;
                if (l > i) {
                    bool up = ((i & k) == 0);
                    u64 a = s[i], b = s[l];
                    bool sw = up ? (a > b) : (a < b);
                    s[i] = sw ? b : a;
                    s[l] = sw ? a : b;
                }
            }
        }
    }

    // Lowest 16 of (L asc, s asc): min-pair makes a bitonic sequence...
    #pragma unroll
    for (int i = 0; i < 16; ++i) {
        u64 a = L[i], b = s[15 - i];
        L[i] = (a < b) ? a : b;
    }
    // ...then bitonic clean, ascending.
    #pragma unroll
    for (int j = 8; j > 0; j >>= 1) {
        #pragma unroll
        for (int i = 0; i < 16; ++i) {
            int l = i ^ j;
            if (l > i) {
                u64 a = L[i], b = L[l];
                bool sw = a > b;
                L[i] = sw ? b : a;
                L[l] = sw ? a : b;
            }
        }
    }

    // tau = d2 of current 16th (inverse of fmap on high word).
    u32 h = (u32)(L[15] >> 32);
    h = (h & 0x80000000u) ? (h ^ 0x80000000u) : ~h;
    tau_f = __uint_as_float(h);

    #pragma unroll
    for (int i = 0; i < 16; ++i) lbuf[i] = SENT;
    n = 0;
}

// d2 bit-exact with the reference gemm lowering:
//   dot = fma(yq*yj, rn(xq*xj)); d2 = rn(rn(sqq+sqj) - rn(2*dot))
#define D2_OF(c) \
    __fsub_rn(__fadd_rn(sqq, (c).z), \
              __fmul_rn(2.0f, __fmaf_rn(yq, (c).y, __fmul_rn(xq, (c).x))))

#define TRY_APPEND(ev, jv)                                   \
    do {                                                     \
        if ((ev) <= tau_f) lbuf[n++] = pack_key((ev), (jv)); \
    } while (0)

// ---------------------------------------------------------------------------
// Kernel 2: KNN top-16, buffered deferred selection.
// One thread per query; 64-thread blocks (512 blocks -> all 148 SMs covered).
// Hot loop: 4-wide unrolled distances (MLP=4) + float threshold gate +
// predicated buffer append. Rare warp-synchronized flush does the sorting.
// ---------------------------------------------------------------------------
__global__ void __launch_bounds__(64)
knn_kernel(float* __restrict__ out_knn)
{
    int tid = blockIdx.x * 64 + threadIdx.x;   // 0 .. B_*N_-1
    int b = tid >> 11;                          // batch
    int q = tid & (N_ - 1);                     // query within batch

    const float4* __restrict__ pk = g_pk + b * N_;
    float4 me = __ldg(&pk[q]);
    float xq = me.x, yq = me.y, sqq = me.z;

    u64 L[16];
    #pragma unroll
    for (int k = 0; k < 16; ++k) L[k] = SENT;

    u64 lbuf[16];                               // local-mem append buffer
    #pragma unroll
    for (int k = 0; k < 16; ++k) lbuf[k] = SENT;
    int n = 0;
    float tau_f = 3.4e38f;

    for (int j = 0; j < N_; j += 4) {
        float4 c0 = __ldg(&pk[j]);
        float4 c1 = __ldg(&pk[j + 1]);
        float4 c2 = __ldg(&pk[j + 2]);
        float4 c3 = __ldg(&pk[j + 3]);

        float e0 = D2_OF(c0);
        float e1 = D2_OF(c1);
        float e2 = D2_OF(c2);
        float e3 = D2_OF(c3);

        // self-exclusion, hoisted to one rare branch per 4-group
        if ((unsigned)(q - j) < 4u) {
            if (q == j)     e0 = 2.0e30f;
            if (q == j + 1) e1 = 2.0e30f;
            if (q == j + 2) e2 = 2.0e30f;
            if (q == j + 3) e3 = 2.0e30f;
        }

        // '<=' (not '<'): an equal-d2 candidate with smaller j must enter
        // (it outranks the current 16th under top_k's stable order); the
        // u64-key flush resolves all ties exactly.
        TRY_APPEND(e0, j);
        TRY_APPEND(e1, j + 1);
        TRY_APPEND(e2, j + 2);
        TRY_APPEND(e3, j + 3);

        // At most 4 appends per group; flush leaves n=0, so n<=12 holds
        // at every check -> buffer (16 slots) can never overflow.
        if (__ballot_sync(0xffffffffu, n >= 13))
            flush16(L, lbuf, n, tau_f);
    }

    flush16(L, lbuf, n, tau_f);                 // final drain

    float* o = out_knn + ((long long)b * N_ + q) * K_;
    #pragma unroll
    for (int k = 0; k < K_; ++k) o[k] = (float)(u32)(L[k] & 0xFFFFFFFFu);
}

// ---------------------------------------------------------------------------
extern "C" void kernel_launch(void* const* d_in, const int* in_sizes, int n_in,
                              void* d_out, int out_size)
{
    const float* coords   = (const float*)d_in[0];
    const float* demands  = (const float*)d_in[1];
    const float* capacity = (const float*)d_in[2];
    const float* Wa       = (const float*)d_in[3];
    const float* ba       = (const float*)d_in[4];
    const float* W1       = (const float*)d_in[5];
    const float* b1       = (const float*)d_in[6];
    const float* W2       = (const float*)d_in[7];
    const float* b2       = (const float*)d_in[8];
    float* out = (float*)d_out;

    encode_kernel<<<dim3(N_ / 256, B_), 256>>>(coords, demands, capacity,
                                               Wa, ba, W1, b1, W2, b2, out);
    knn_kernel<<<dim3(B_ * N_ / 64), 64>>>(out + KNN_OFF);
}

// round 7
// speedup vs baseline: 1.7870x; 1.2325x over previous
#include <cuda_runtime.h>
#include <math.h>

#define B_   16
#define N_   2048
#define K_   16
#define EPS_ 1e-8f

// Output layout (tuple flattened in order):
//   psi_prime : B*N*2  floats  @ 0
//   features  : B*N*5  floats  @ 65536
//   knn_idx   : B*N*16 floats  @ 229376
#define PSI_OFF  0
#define FEAT_OFF (B_ * N_ * 2)
#define KNN_OFF  (B_ * N_ * 2 + B_ * N_ * 5)

typedef unsigned long long u64;
typedef unsigned int u32;

#define SENT 0xFFFFFFFFFFFFFFFFull
#define SUB_ (N_ / 2)          // candidates per thread (2 threads/query)

// SOA candidate data for the KNN kernel.
__device__ float g_x [B_ * N_];
__device__ float g_y [B_ * N_];
__device__ float g_sq[B_ * N_];

// ---------------------------------------------------------------------------
// Kernel 1: features + encoder (tiny MLP) + SOA coord scratch.
// ---------------------------------------------------------------------------
__global__ void encode_kernel(const float* __restrict__ coords,
                              const float* __restrict__ demands,
                              const float* __restrict__ capacity,
                              const float* __restrict__ Wa,
                              const float* __restrict__ ba,
                              const float* __restrict__ W1,
                              const float* __restrict__ b1,
                              const float* __restrict__ W2,
                              const float* __restrict__ b2,
                              float* __restrict__ out)
{
    int b = blockIdx.y;
    int n = blockIdx.x * blockDim.x + threadIdx.x;
    if (n >= N_) return;

    __shared__ float sWa[10], sba[2], sW1[80], sb1[16], sW2[16], sb2_s;
    int t = threadIdx.x;
    if (t < 10) sWa[t] = Wa[t];
    if (t < 2)  sba[t] = ba[t];
    if (t < 80) sW1[t] = W1[t];
    if (t < 16) { sb1[t] = b1[t]; sW2[t] = W2[t]; }
    if (t == 0) sb2_s = b2[0];
    __syncthreads();

    const float* cp = coords + ((long long)b * N_ + n) * 2;
    float x = cp[0], y = cp[1];

    // SOA scratch for knn; sq with the reference's rounding:
    // rn(rn(x*x) + rn(y*y))
    float sq = __fadd_rn(__fmul_rn(x, x), __fmul_rn(y, y));
    g_x [b * N_ + n] = x;
    g_y [b * N_ + n] = y;
    g_sq[b * N_ + n] = sq;

    float dx0 = coords[(long long)b * N_ * 2 + 0];
    float dy0 = coords[(long long)b * N_ * 2 + 1];
    float rx = x - dx0, ry = y - dy0;
    float dist = sqrtf(rx * rx + ry * ry + EPS_);
    float ang  = atan2f(ry, rx);
    float dem  = demands[(long long)b * N_ + n] / capacity[b];

    float f0 = x, f1 = y, f2 = dem, f3 = dist, f4 = ang;

    float* fo = out + FEAT_OFF + ((long long)b * N_ + n) * 5;
    fo[0] = f0; fo[1] = f1; fo[2] = f2; fo[3] = f3; fo[4] = f4;

    float p0 = sba[0] + f0*sWa[0] + f1*sWa[1] + f2*sWa[2] + f3*sWa[3] + f4*sWa[4];
    float p1 = sba[1] + f0*sWa[5] + f1*sWa[6] + f2*sWa[7] + f3*sWa[8] + f4*sWa[9];
    float nrm = sqrtf(p0 * p0 + p1 * p1);
    float inv = 1.0f / (nrm + EPS_);
    p0 *= inv; p1 *= inv;

    float theta = sb2_s;
    #pragma unroll
    for (int h = 0; h < 16; ++h) {
        const float* w = sW1 + h * 5;
        float a = sb1[h] + f0*w[0] + f1*w[1] + f2*w[2] + f3*w[3] + f4*w[4];
        theta += tanhf(a) * sW2[h];
    }
    float c = cosf(theta), s = sinf(theta);

    float* po = out + PSI_OFF + ((long long)b * N_ + n) * 2;
    po[0] = c * p0 - s * p1;
    po[1] = s * p0 + c * p1;
}

// ---------------------------------------------------------------------------
// KNN helpers
// ---------------------------------------------------------------------------

// Monotone map: float bits -> u32 whose unsigned order == float order.
__device__ __forceinline__ u32 fmap(u32 b) {
    return b ^ ((u32)((int)b >> 31) | 0x80000000u);
}

// Flush: convert raw (f32bits<<32|j) buffer entries to total-order keys,
// bitonic-sort-16, merge into sorted L (min-pair + clean), tighten tau.
// Tie handling exact: keys are (fmap(d2), j) lexicographic.
__device__ __forceinline__ void flush16(u64* L, const u64* lbuf, int& n,
                                        float& tau_f)
{
    u64 s[16];
    #pragma unroll
    for (int i = 0; i < 16; ++i) {
        u64 raw = lbuf[i];
        u64 key = ((u64)fmap((u32)(raw >> 32)) << 32) | (u32)raw;
        s[i] = (i < n) ? key : SENT;
    }

    // Bitonic sort 16, ascending (R5-proven network).
    #pragma unroll
    for (int k = 2; k <= 16; k <<= 1) {
        #pragma unroll
        for (int j = k >> 1; j > 0; j >>= 1) {
            #pragma unroll
            for (int i = 0; i < 16; ++i) {
                int l = i ^ j;
                if (l > i) {
                    bool up = ((i & k) == 0);
                    u64 a = s[i], b = s[l];
                    bool sw = up ? (a > b) : (a < b);
                    s[i] = sw ? b : a;
                    s[l] = sw ? a : b;
                }
            }
        }
    }

    // Lowest 16 of (L asc, s asc): min-pair -> bitonic, then clean.
    #pragma unroll
    for (int i = 0; i < 16; ++i) {
        u64 a = L[i], b = s[15 - i];
        L[i] = (a < b) ? a : b;
    }
    #pragma unroll
    for (int j = 8; j > 0; j >>= 1) {
        #pragma unroll
        for (int i = 0; i < 16; ++i) {
            int l = i ^ j;
            if (l > i) {
                u64 a = L[i], b = L[l];
                bool sw = a > b;
                L[i] = sw ? b : a;
                L[l] = sw ? a : b;
            }
        }
    }

    // tau = d2 of current 16th (inverse fmap on high word). L is always
    // full of real keys by the first flush (first flush fires while
    // tau=inf, so every lane appended its first 16 candidates).
    u32 h = (u32)(L[15] >> 32);
    h = (h & 0x80000000u) ? (h ^ 0x80000000u) : ~h;
    tau_f = __uint_as_float(h);
    n = 0;
}

// d2 bit-exact with the reference:
//   dot = fma(yq*yj, rn(xq*xj));  s = rn(sqq+sqj)
//   ref: rn(s - rn(2*dot)) == rn(s - 2*dot)  [2*dot is exact]
//      == fma(-2, dot, s)
#define D2_OF(xv, yv, sv) \
    __fmaf_rn(-2.0f, __fmaf_rn(yq, (yv), __fmul_rn(xq, (xv))), \
              __fadd_rn(sqq, (sv)))

// ---------------------------------------------------------------------------
// Kernel 2: KNN top-16, buffered deferred selection, 2 threads per query.
// Thread p of a query scans candidate block [p*1024, (p+1)*1024), unroll 8,
// SOA float4 loads (6 LDG.128 / 8 candidates, MLP=6). Appends store raw
// (d2bits<<32)|j; fmap deferred to flush. Partner lanes (lane^1) merge their
// sorted per-half top-16 lists at the end via shfl min-pair + bitonic clean.
// ---------------------------------------------------------------------------
__global__ void __launch_bounds__(128)
knn_kernel(float* __restrict__ out_knn)
{
    int qid = blockIdx.x * 64 + (threadIdx.x >> 1);  // global query id
    int p   = threadIdx.x & 1;                       // candidate-half
    int b   = qid >> 11;
    int q   = qid & (N_ - 1);

    const float* bx = g_x  + b * N_;
    const float* by = g_y  + b * N_;
    const float* bs = g_sq + b * N_;

    float xq  = __ldg(&bx[q]);
    float yq  = __ldg(&by[q]);
    float sqq = __ldg(&bs[q]);

    const float4* x4 = (const float4*)(bx + p * SUB_);
    const float4* y4 = (const float4*)(by + p * SUB_);
    const float4* s4 = (const float4*)(bs + p * SUB_);
    int jbase = p * SUB_;

    u64 L[16];
    #pragma unroll
    for (int k = 0; k < 16; ++k) L[k] = SENT;

    u64 lbuf[16];
    int n = 0;
    float tau_f = 3.4e38f;

    #define TRY_APPEND(ev, jv) \
        do { if ((ev) <= tau_f) \
            lbuf[n++] = ((u64)__float_as_uint(ev) << 32) | (u32)(jv); } while (0)

    for (int i = 0; i < SUB_ / 8; ++i) {
        float4 xa = __ldg(&x4[2 * i]);
        float4 xb = __ldg(&x4[2 * i + 1]);
        float4 ya = __ldg(&y4[2 * i]);
        float4 yb = __ldg(&y4[2 * i + 1]);
        float4 sa = __ldg(&s4[2 * i]);
        float4 sb = __ldg(&s4[2 * i + 1]);

        float e0 = D2_OF(xa.x, ya.x, sa.x);
        float e1 = D2_OF(xa.y, ya.y, sa.y);
        float e2 = D2_OF(xa.z, ya.z, sa.z);
        float e3 = D2_OF(xa.w, ya.w, sa.w);
        float e4 = D2_OF(xb.x, yb.x, sb.x);
        float e5 = D2_OF(xb.y, yb.y, sb.y);
        float e6 = D2_OF(xb.z, yb.z, sb.z);
        float e7 = D2_OF(xb.w, yb.w, sb.w);

        int j0 = jbase + 8 * i;
        // self-exclusion, one rare branch per 8-window
        if ((unsigned)(q - j0) < 8u) {
            int r = q - j0;
            if (r == 0) e0 = 2.0e30f;  if (r == 1) e1 = 2.0e30f;
            if (r == 2) e2 = 2.0e30f;  if (r == 3) e3 = 2.0e30f;
            if (r == 4) e4 = 2.0e30f;  if (r == 5) e5 = 2.0e30f;
            if (r == 6) e6 = 2.0e30f;  if (r == 7) e7 = 2.0e30f;
        }

        // '<=' so equal-d2/smaller-j candidates always enter; the u64-key
        // flush resolves ties exactly (top_k stable order).
        TRY_APPEND(e0, j0);     TRY_APPEND(e1, j0 + 1);
        TRY_APPEND(e2, j0 + 2); TRY_APPEND(e3, j0 + 3);
        TRY_APPEND(e4, j0 + 4); TRY_APPEND(e5, j0 + 5);
        TRY_APPEND(e6, j0 + 6); TRY_APPEND(e7, j0 + 7);

        // n <= 8 at entry (post-flush or post-check), +8 -> 16 max: no
        // overflow of lbuf[16]. Warp-synchronized flush keeps lanes aligned.
        if (__ballot_sync(0xffffffffu, n >= 9))
            flush16(L, lbuf, n, tau_f);
    }

    flush16(L, lbuf, n, tau_f);   // drain

    // Merge partner halves (lane^1): min-pair against partner's reversed
    // sorted list -> lowest-16 as bitonic sequence -> clean. Both lanes end
    // with the identical full top-16.
    #pragma unroll
    for (int i = 0; i < 16; ++i) {
        u64 other = __shfl_xor_sync(0xffffffffu, L[15 - i], 1);
        u64 a = L[i];
        L[i] = (a < other) ? a : other;
    }
    #pragma unroll
    for (int j = 8; j > 0; j >>= 1) {
        #pragma unroll
        for (int i = 0; i < 16; ++i) {
            int l = i ^ j;
            if (l > i) {
                u64 a = L[i], b2 = L[l];
                bool sw = a > b2;
                L[i] = sw ? b2 : a;
                L[l] = sw ? a : b2;
            }
        }
    }

    // Each partner lane writes half the 16 outputs.
    float* o = out_knn + ((long long)b * N_ + q) * K_;
    #pragma unroll
    for (int k = 0; k < 8; ++k) {
        int kk = p * 8 + k;
        o[kk] = (float)(u32)(L[kk] & 0xFFFFFFFFu);
    }
    #undef TRY_APPEND
}

// ---------------------------------------------------------------------------
extern "C" void kernel_launch(void* const* d_in, const int* in_sizes, int n_in,
                              void* d_out, int out_size)
{
    const float* coords   = (const float*)d_in[0];
    const float* demands  = (const float*)d_in[1];
    const float* capacity = (const float*)d_in[2];
    const float* Wa       = (const float*)d_in[3];
    const float* ba       = (const float*)d_in[4];
    const float* W1       = (const float*)d_in[5];
    const float* b1       = (const float*)d_in[6];
    const float* W2       = (const float*)d_in[7];
    const float* b2       = (const float*)d_in[8];
    float* out = (float*)d_out;

    encode_kernel<<<dim3(N_ / 256, B_), 256>>>(coords, demands, capacity,
                                               Wa, ba, W1, b1, W2, b2, out);
    // B*N queries x 2 threads each; 128-thread blocks (64 queries/block)
    knn_kernel<<<dim3(B_ * N_ * 2 / 128), 128>>>(out + KNN_OFF);
}